// round 2
// baseline (speedup 1.0000x reference)
#include <cuda_runtime.h>
#include <math.h>

#define C_DIM 256
#define CQK   32
#define NVOX  4096
#define BATCH 4

// Scratch (static device globals; no allocation anywhere)
__device__ float g_q[BATCH * NVOX * CQK];   // [b][n][cqk]
__device__ float g_k[BATCH * NVOX * CQK];   // [b][m][cqk]
__device__ float g_v[BATCH * NVOX * C_DIM]; // [b][m][c]

// ---------------------------------------------------------------------------
// Projection kernel: computes q = Wq x + bq, k = Wk x + bk, v = Wv x + bv
// Treated as one GEMM with stacked output rows r in [0,320):
//   r <  32 -> Wq row r        -> g_q
//   r <  64 -> Wk row r-32     -> g_k
//   r < 320 -> Wv row r-64     -> g_v
// Block computes a [64 out x 128 vox] tile, K=256 in chunks of 32.
// ---------------------------------------------------------------------------
#define PT_N 128
#define PT_M 64
#define PT_K 32
#define WS_PITCH 64

__global__ __launch_bounds__(256) void proj_kernel(
    const float* __restrict__ x,
    const float* __restrict__ Wq, const float* __restrict__ bq,
    const float* __restrict__ Wk, const float* __restrict__ bk,
    const float* __restrict__ Wv, const float* __restrict__ bv)
{
    __shared__ float ws[PT_K * WS_PITCH];  // [k][o]
    __shared__ float xs[PT_K * PT_N];      // [k][n]

    const int tid = threadIdx.x;
    const int n0  = blockIdx.x * PT_N;
    const int og  = blockIdx.y;            // output group (5 groups of 64)
    const int b   = blockIdx.z;
    const int tx  = tid & 7;               // 8 out-groups of 8 outputs
    const int ty  = tid >> 3;              // 32 vox-groups of 4 voxels

    float acc[8][4];
#pragma unroll
    for (int i = 0; i < 8; i++)
#pragma unroll
        for (int j = 0; j < 4; j++) acc[i][j] = 0.f;

    const float* xb = x + (size_t)b * C_DIM * NVOX;

    for (int kk = 0; kk < C_DIM; kk += PT_K) {
        // weights: ws[k][o]  (r = og*64 + o), coalesced over c
        for (int idx = tid; idx < PT_M * PT_K; idx += 256) {
            int k = idx & 31, o = idx >> 5;
            int r = og * PT_M + o;
            const float* wrow;
            if (r < CQK)            wrow = Wq + (size_t)r * C_DIM;
            else if (r < 2 * CQK)   wrow = Wk + (size_t)(r - CQK) * C_DIM;
            else                    wrow = Wv + (size_t)(r - 2 * CQK) * C_DIM;
            ws[k * WS_PITCH + o] = wrow[kk + k];
        }
        // x tile: xs[k][n], float4 coalesced
        for (int idx = tid; idx < PT_K * PT_N / 4; idx += 256) {
            int k = idx >> 5, n4 = idx & 31;
            float4 v = *(const float4*)(xb + (size_t)(kk + k) * NVOX + n0 + n4 * 4);
            *(float4*)(xs + k * PT_N + n4 * 4) = v;
        }
        __syncthreads();

#pragma unroll
        for (int k = 0; k < PT_K; k++) {
            const float* wr = ws + k * WS_PITCH + tx * 8;
            float4 w0 = *(const float4*)(wr);
            float4 w1 = *(const float4*)(wr + 4);
            float4 xv = *(const float4*)(xs + k * PT_N + ty * 4);
            float wv[8] = {w0.x, w0.y, w0.z, w0.w, w1.x, w1.y, w1.z, w1.w};
            float xr[4] = {xv.x, xv.y, xv.z, xv.w};
#pragma unroll
            for (int i = 0; i < 8; i++)
#pragma unroll
                for (int j = 0; j < 4; j++)
                    acc[i][j] += wv[i] * xr[j];
        }
        __syncthreads();
    }

    // epilogue: bias + scatter into q/k/v scratch
#pragma unroll
    for (int i = 0; i < 8; i++) {
        int r = og * PT_M + tx * 8 + i;
#pragma unroll
        for (int j = 0; j < 4; j++) {
            int n = n0 + ty * 4 + j;
            float v = acc[i][j];
            if (r < CQK) {
                g_q[((size_t)b * NVOX + n) * CQK + r] = v + bq[r];
            } else if (r < 2 * CQK) {
                g_k[((size_t)b * NVOX + n) * CQK + (r - CQK)] = v + bk[r - CQK];
            } else {
                g_v[((size_t)b * NVOX + n) * C_DIM + (r - 2 * CQK)] = v + bv[r - 2 * CQK];
            }
        }
    }
}

// ---------------------------------------------------------------------------
// Fused attention kernel (streaming softmax), fp32.
// One CTA handles 64 query rows of one batch. Loops m in tiles of 64.
//   S = Q Kt (Cqk=32), online softmax, O = O*corr + P V (C=256)
// Epilogue: out[b,c,n] = x[b,c,n] + O[n,c]/l[n]
// ---------------------------------------------------------------------------
#define BM 64
#define BK 64
#define QP 36    // Q/K smem row pitch (conflict-free float4 across lanes)
#define PP 65    // P pitch (conflict-free scalar row scans)
#define OP 260   // O pitch (16B aligned, mild conflicts only in epilogue)

#define ATTN_SMEM_FLOATS (BM*QP + BM*QP + BM*C_DIM + BM*PP + BM*OP + 3*BM)
#define ATTN_SMEM_BYTES  (ATTN_SMEM_FLOATS * 4)

__global__ __launch_bounds__(256) void attn_kernel(
    const float* __restrict__ x, float* __restrict__ out)
{
    extern __shared__ float sm[];
    float* Qs = sm;                  // [BM][QP]
    float* Ks = Qs + BM * QP;        // [BK][QP]
    float* Vs = Ks + BM * QP;        // [BK][C_DIM]
    float* Ps = Vs + BM * C_DIM;     // [BM][PP]
    float* Os = Ps + BM * PP;        // [BM][OP]
    float* ms_ = Os + BM * OP;       // [BM] running max
    float* ls_ = ms_ + BM;           // [BM] running sum
    float* cs_ = ls_ + BM;           // [BM] correction

    const int tid = threadIdx.x;
    const int b   = blockIdx.y;
    const int n0  = blockIdx.x * BM;
    const int tx  = tid & 15;        // 16 col-groups
    const int ty  = tid >> 4;        // 16 row-groups

    // init O accumulator + stats
    for (int idx = tid; idx < BM * OP; idx += 256) Os[idx] = 0.f;
    if (tid < BM) { ms_[tid] = -INFINITY; ls_[tid] = 0.f; }

    // load Q tile once
    const float* qb = g_q + (size_t)b * NVOX * CQK;
    for (int idx = tid; idx < BM * CQK / 4; idx += 256) {
        int r = idx >> 3, k4 = idx & 7;
        float4 v = *(const float4*)(qb + (size_t)(n0 + r) * CQK + k4 * 4);
        *(float4*)(Qs + r * QP + k4 * 4) = v;
    }
    __syncthreads();

    const float* kb = g_k + (size_t)b * NVOX * CQK;
    const float* vb = g_v + (size_t)b * NVOX * C_DIM;

    for (int m0 = 0; m0 < NVOX; m0 += BK) {
        // load K tile
        for (int idx = tid; idx < BK * CQK / 4; idx += 256) {
            int r = idx >> 3, k4 = idx & 7;
            float4 v = *(const float4*)(kb + (size_t)(m0 + r) * CQK + k4 * 4);
            *(float4*)(Ks + r * QP + k4 * 4) = v;
        }
        // load V tile
        for (int idx = tid; idx < BK * C_DIM / 4; idx += 256) {
            int r = idx >> 6, c4 = idx & 63;
            float4 v = *(const float4*)(vb + (size_t)(m0 + r) * C_DIM + c4 * 4);
            *(float4*)(Vs + r * C_DIM + c4 * 4) = v;
        }
        __syncthreads();

        // ---- S = Q Kt : thread computes rows {ty+16i}, cols {tx+16j}
        {
            float s[4][4];
#pragma unroll
            for (int i = 0; i < 4; i++)
#pragma unroll
                for (int j = 0; j < 4; j++) s[i][j] = 0.f;

#pragma unroll
            for (int k4 = 0; k4 < CQK / 4; k4++) {
                float4 qv[4], kv[4];
#pragma unroll
                for (int i = 0; i < 4; i++)
                    qv[i] = *(const float4*)(Qs + (ty + 16 * i) * QP + k4 * 4);
#pragma unroll
                for (int j = 0; j < 4; j++)
                    kv[j] = *(const float4*)(Ks + (tx + 16 * j) * QP + k4 * 4);
#pragma unroll
                for (int i = 0; i < 4; i++)
#pragma unroll
                    for (int j = 0; j < 4; j++)
                        s[i][j] += qv[i].x * kv[j].x + qv[i].y * kv[j].y
                                 + qv[i].z * kv[j].z + qv[i].w * kv[j].w;
            }
#pragma unroll
            for (int i = 0; i < 4; i++)
#pragma unroll
                for (int j = 0; j < 4; j++)
                    Ps[(ty + 16 * i) * PP + tx + 16 * j] = s[i][j];
        }
        __syncthreads();

        // ---- online softmax (one thread per row)
        if (tid < BM) {
            const int r = tid;
            float mo = ms_[r];
            float mx = mo;
            for (int c = 0; c < BK; c++) mx = fmaxf(mx, Ps[r * PP + c]);
            float corr = __expf(mo - mx);
            float sum = 0.f;
            for (int c = 0; c < BK; c++) {
                float p = __expf(Ps[r * PP + c] - mx);
                Ps[r * PP + c] = p;
                sum += p;
            }
            ls_[r] = ls_[r] * corr + sum;
            ms_[r] = mx;
            cs_[r] = corr;
        }
        __syncthreads();

        // ---- O = O*corr + P @ V : thread rows {ty+16i}, cols {tx*4+64k .. +3}
        {
            float acc[4][16];
#pragma unroll
            for (int i = 0; i < 4; i++)
#pragma unroll
                for (int j = 0; j < 16; j++) acc[i][j] = 0.f;

            for (int m = 0; m < BK; m++) {
                float p[4];
#pragma unroll
                for (int i = 0; i < 4; i++)
                    p[i] = Ps[(ty + 16 * i) * PP + m];
                float4 vv[4];
#pragma unroll
                for (int k = 0; k < 4; k++)
                    vv[k] = *(const float4*)(Vs + m * C_DIM + tx * 4 + 64 * k);
#pragma unroll
                for (int i = 0; i < 4; i++) {
#pragma unroll
                    for (int k = 0; k < 4; k++) {
                        acc[i][k * 4 + 0] += p[i] * vv[k].x;
                        acc[i][k * 4 + 1] += p[i] * vv[k].y;
                        acc[i][k * 4 + 2] += p[i] * vv[k].z;
                        acc[i][k * 4 + 3] += p[i] * vv[k].w;
                    }
                }
            }
#pragma unroll
            for (int i = 0; i < 4; i++) {
                float co = cs_[ty + 16 * i];
#pragma unroll
                for (int k = 0; k < 4; k++) {
                    float4* op = (float4*)(Os + (ty + 16 * i) * OP + tx * 4 + 64 * k);
                    float4 o = *op;
                    o.x = o.x * co + acc[i][k * 4 + 0];
                    o.y = o.y * co + acc[i][k * 4 + 1];
                    o.z = o.z * co + acc[i][k * 4 + 2];
                    o.w = o.w * co + acc[i][k * 4 + 3];
                    *op = o;
                }
            }
        }
        __syncthreads();
    }

    // ---- epilogue: out[b,c,n0+r] = x + O[r][c] / l[r]   (coalesced over r)
    const float* xb = x + (size_t)b * C_DIM * NVOX;
    float* ob = out + (size_t)b * C_DIM * NVOX;
    for (int idx = tid; idx < BM * C_DIM; idx += 256) {
        int r = idx & 63, c = idx >> 6;
        float invl = 1.f / ls_[r];
        size_t g = (size_t)c * NVOX + n0 + r;
        ob[g] = xb[g] + Os[r * OP + c] * invl;
    }
}

// ---------------------------------------------------------------------------
extern "C" void kernel_launch(void* const* d_in, const int* in_sizes, int n_in,
                              void* d_out, int out_size)
{
    const float* x  = (const float*)d_in[0];
    const float* Wq = (const float*)d_in[1];
    const float* bq = (const float*)d_in[2];
    const float* Wk = (const float*)d_in[3];
    const float* bk = (const float*)d_in[4];
    const float* Wv = (const float*)d_in[5];
    const float* bv = (const float*)d_in[6];
    float* out = (float*)d_out;

    // QKV projections
    proj_kernel<<<dim3(NVOX / PT_N, 5, BATCH), 256>>>(x, Wq, bq, Wk, bk, Wv, bv);

    // fused attention + residual
    cudaFuncSetAttribute(attn_kernel,
                         cudaFuncAttributeMaxDynamicSharedMemorySize,
                         ATTN_SMEM_BYTES);
    attn_kernel<<<dim3(NVOX / BM, BATCH), 256, ATTN_SMEM_BYTES>>>(x, out);
}

// round 4
// speedup vs baseline: 4.3702x; 4.3702x over previous
#include <cuda_runtime.h>
#include <cuda_bf16.h>
#include <stdint.h>
#include <math.h>

#define C_DIM 256
#define CQK   32
#define NVOX  4096
#define BATCH 4

// bf16 scratch (static device globals; no allocation anywhere)
__device__ __nv_bfloat16 g_q[BATCH * NVOX * CQK];    // [b][n][cqk]
__device__ __nv_bfloat16 g_k[BATCH * NVOX * CQK];    // [b][m][cqk]
__device__ __nv_bfloat16 g_v[BATCH * C_DIM * NVOX];  // [b][c][m]  (transposed!)

// ===========================================================================
// Projection kernel: fp32 math, bf16 outputs. V written TRANSPOSED [b][c][m].
// ===========================================================================
#define PT_N 128
#define PT_M 64
#define PT_K 32
#define WS_PITCH 64

__global__ __launch_bounds__(256) void proj_kernel(
    const float* __restrict__ x,
    const float* __restrict__ Wq, const float* __restrict__ bq,
    const float* __restrict__ Wk, const float* __restrict__ bk,
    const float* __restrict__ Wv, const float* __restrict__ bv)
{
    __shared__ float ws[PT_K * WS_PITCH];
    __shared__ float xs[PT_K * PT_N];

    const int tid = threadIdx.x;
    const int n0  = blockIdx.x * PT_N;
    const int og  = blockIdx.y;
    const int b   = blockIdx.z;
    const int tx  = tid & 7;
    const int ty  = tid >> 3;

    float acc[8][4];
#pragma unroll
    for (int i = 0; i < 8; i++)
#pragma unroll
        for (int j = 0; j < 4; j++) acc[i][j] = 0.f;

    const float* xb = x + (size_t)b * C_DIM * NVOX;

    for (int kk = 0; kk < C_DIM; kk += PT_K) {
        for (int idx = tid; idx < PT_M * PT_K; idx += 256) {
            int k = idx & 31, o = idx >> 5;
            int r = og * PT_M + o;
            const float* wrow;
            if (r < CQK)          wrow = Wq + (size_t)r * C_DIM;
            else if (r < 2 * CQK) wrow = Wk + (size_t)(r - CQK) * C_DIM;
            else                  wrow = Wv + (size_t)(r - 2 * CQK) * C_DIM;
            ws[k * WS_PITCH + o] = wrow[kk + k];
        }
        for (int idx = tid; idx < PT_K * PT_N / 4; idx += 256) {
            int k = idx >> 5, n4 = idx & 31;
            float4 v = *(const float4*)(xb + (size_t)(kk + k) * NVOX + n0 + n4 * 4);
            *(float4*)(xs + k * PT_N + n4 * 4) = v;
        }
        __syncthreads();

#pragma unroll
        for (int k = 0; k < PT_K; k++) {
            const float* wr = ws + k * WS_PITCH + tx * 8;
            float4 w0 = *(const float4*)(wr);
            float4 w1 = *(const float4*)(wr + 4);
            float4 xv = *(const float4*)(xs + k * PT_N + ty * 4);
            float wv[8] = {w0.x, w0.y, w0.z, w0.w, w1.x, w1.y, w1.z, w1.w};
            float xr[4] = {xv.x, xv.y, xv.z, xv.w};
#pragma unroll
            for (int i = 0; i < 8; i++)
#pragma unroll
                for (int j = 0; j < 4; j++)
                    acc[i][j] += wv[i] * xr[j];
        }
        __syncthreads();
    }

#pragma unroll
    for (int i = 0; i < 8; i++) {
        int r = og * PT_M + tx * 8 + i;
#pragma unroll
        for (int j = 0; j < 4; j++) {
            int n = n0 + ty * 4 + j;
            float v = acc[i][j];
            if (r < CQK) {
                g_q[((size_t)b * NVOX + n) * CQK + r] = __float2bfloat16(v + bq[r]);
            } else if (r < 2 * CQK) {
                g_k[((size_t)b * NVOX + n) * CQK + (r - CQK)] = __float2bfloat16(v + bk[r - CQK]);
            } else {
                int c = r - 2 * CQK;
                g_v[((size_t)b * C_DIM + c) * NVOX + n] = __float2bfloat16(v + bv[c]);
            }
        }
    }
}

// ===========================================================================
// Attention kernel: mma.sync.m16n8k16 bf16 (FA2 style, max-free softmax).
// 8 warps x 16 q-rows = BM 128. BK = 128 keys/iter, 32 iters.
// ===========================================================================
#define KP_B  80    // Ks row pitch bytes (40 bf16) - conflict-free B-frag loads
#define VP_B  272   // Vt row pitch bytes (136 bf16) - conflict-free B-frag loads
#define KS_BYTES (128 * KP_B)          // 10240
#define VT_BYTES (256 * VP_B)          // 69632
#define ATTN_SMEM (KS_BYTES + VT_BYTES)

__device__ __forceinline__ void hmma16816(float* c, const uint32_t* a,
                                          uint32_t b0, uint32_t b1)
{
    asm volatile(
        "mma.sync.aligned.m16n8k16.row.col.f32.bf16.bf16.f32 "
        "{%0,%1,%2,%3}, {%4,%5,%6,%7}, {%8,%9}, {%0,%1,%2,%3};"
        : "+f"(c[0]), "+f"(c[1]), "+f"(c[2]), "+f"(c[3])
        : "r"(a[0]), "r"(a[1]), "r"(a[2]), "r"(a[3]), "r"(b0), "r"(b1));
}

__global__ __launch_bounds__(256, 1) void attn_kernel(
    const float* __restrict__ x, float* __restrict__ out)
{
    extern __shared__ __align__(16) char smem[];
    char* Ks = smem;             // [128 keys][40 bf16] (32 used)
    char* Vt = smem + KS_BYTES;  // [256 c][136 bf16] (128 used)

    const int tid  = threadIdx.x;
    const int w    = tid >> 5;
    const int lane = tid & 31;
    const int g    = lane >> 2;   // row group 0..7
    const int tig  = lane & 3;    // thread-in-group

    const int b    = blockIdx.y;
    const int n0   = blockIdx.x * 128;
    const int wrow = w * 16;

    const __nv_bfloat16* qb = g_q + (size_t)b * NVOX * CQK;
    const __nv_bfloat16* kb = g_k + (size_t)b * NVOX * CQK;
    const __nv_bfloat16* vb = g_v + (size_t)b * C_DIM * NVOX;

    // ---- Q fragments (held all kernel): A-frags for 2 k-tiles of CQK=32
    uint32_t qa[2][4];
    {
        const int r0 = n0 + wrow + g;
#pragma unroll
        for (int kt = 0; kt < 2; kt++) {
            const int cb = kt * 16 + 2 * tig;
            qa[kt][0] = *(const uint32_t*)(qb + (size_t)r0 * CQK + cb);
            qa[kt][1] = *(const uint32_t*)(qb + (size_t)(r0 + 8) * CQK + cb);
            qa[kt][2] = *(const uint32_t*)(qb + (size_t)r0 * CQK + cb + 8);
            qa[kt][3] = *(const uint32_t*)(qb + (size_t)(r0 + 8) * CQK + cb + 8);
        }
    }

    float oacc[32][4];
#pragma unroll
    for (int j = 0; j < 32; j++)
#pragma unroll
        for (int q = 0; q < 4; q++) oacc[j][q] = 0.f;

    float ls0 = 0.f, ls1 = 0.f;   // row sums (rows g and g+8)

    for (int it = 0; it < 32; ++it) {
        const int m0 = it * 128;

        // ---- load K tile: 128 keys x 64B
        for (int i = tid; i < 512; i += 256) {
            int r = i >> 2, c = i & 3;
            uint4 v = *(const uint4*)(kb + (size_t)(m0 + r) * CQK + c * 8);
            *(uint4*)(Ks + r * KP_B + c * 16) = v;
        }
        // ---- load V tile (transposed source): 256 c-rows x 256B
        for (int i = tid; i < 4096; i += 256) {
            int r = i >> 4, c = i & 15;
            uint4 v = *(const uint4*)(vb + (size_t)r * NVOX + m0 + c * 8);
            *(uint4*)(Vt + r * VP_B + c * 16) = v;
        }
        __syncthreads();

        // ---- S = Q K^T : 16 n8-tiles x 2 k-tiles
        float sacc[16][4];
#pragma unroll
        for (int j = 0; j < 16; j++) {
#pragma unroll
            for (int q = 0; q < 4; q++) sacc[j][q] = 0.f;
            const char* base = Ks + (8 * j + g) * KP_B + tig * 4;
            uint32_t b0 = *(const uint32_t*)(base);
            uint32_t b1 = *(const uint32_t*)(base + 16);
            uint32_t b2 = *(const uint32_t*)(base + 32);
            uint32_t b3 = *(const uint32_t*)(base + 48);
            hmma16816(sacc[j], qa[0], b0, b1);
            hmma16816(sacc[j], qa[1], b2, b3);
        }

        // ---- max-free softmax: P = exp(S); pack into A-frags for PV
        uint32_t pa[8][4];
#pragma unroll
        for (int kt = 0; kt < 8; kt++) {
            float e00 = __expf(sacc[2 * kt][0]);
            float e01 = __expf(sacc[2 * kt][1]);
            float e02 = __expf(sacc[2 * kt][2]);
            float e03 = __expf(sacc[2 * kt][3]);
            float e10 = __expf(sacc[2 * kt + 1][0]);
            float e11 = __expf(sacc[2 * kt + 1][1]);
            float e12 = __expf(sacc[2 * kt + 1][2]);
            float e13 = __expf(sacc[2 * kt + 1][3]);
            ls0 += e00 + e01 + e10 + e11;
            ls1 += e02 + e03 + e12 + e13;
            __nv_bfloat162 h;
            h = __float22bfloat162_rn(make_float2(e00, e01));
            pa[kt][0] = *reinterpret_cast<uint32_t*>(&h);
            h = __float22bfloat162_rn(make_float2(e02, e03));
            pa[kt][1] = *reinterpret_cast<uint32_t*>(&h);
            h = __float22bfloat162_rn(make_float2(e10, e11));
            pa[kt][2] = *reinterpret_cast<uint32_t*>(&h);
            h = __float22bfloat162_rn(make_float2(e12, e13));
            pa[kt][3] = *reinterpret_cast<uint32_t*>(&h);
        }

        // ---- O += P V : 32 c n8-tiles x 8 k-tiles
#pragma unroll
        for (int j = 0; j < 32; j++) {
            const char* vbase = Vt + (8 * j + g) * VP_B + tig * 4;
#pragma unroll
            for (int kt = 0; kt < 8; kt++) {
                uint32_t b0 = *(const uint32_t*)(vbase + kt * 32);
                uint32_t b1 = *(const uint32_t*)(vbase + kt * 32 + 16);
                hmma16816(oacc[j], pa[kt], b0, b1);
            }
        }
        __syncthreads();
    }

    // ---- row-sum reduction within lane quad (lanes share row group g)
    ls0 += __shfl_xor_sync(0xFFFFFFFFu, ls0, 1);
    ls0 += __shfl_xor_sync(0xFFFFFFFFu, ls0, 2);
    ls1 += __shfl_xor_sync(0xFFFFFFFFu, ls1, 1);
    ls1 += __shfl_xor_sync(0xFFFFFFFFu, ls1, 2);
    const float inv0 = 1.f / ls0;
    const float inv1 = 1.f / ls1;

    // ---- epilogue: out[b,c,n] = x + O/l
    const float* xb = x + (size_t)b * C_DIM * NVOX;
    float* ob = out + (size_t)b * C_DIM * NVOX;
    const int ng  = n0 + wrow + g;
    const int ng8 = ng + 8;
#pragma unroll
    for (int j = 0; j < 32; j++) {
        const int c0 = 8 * j + 2 * tig;
        size_t g0 = (size_t)c0 * NVOX + ng;
        size_t g1 = (size_t)c0 * NVOX + ng8;
        ob[g0]        = xb[g0]        + oacc[j][0] * inv0;
        ob[g0 + NVOX] = xb[g0 + NVOX] + oacc[j][1] * inv0;
        ob[g1]        = xb[g1]        + oacc[j][2] * inv1;
        ob[g1 + NVOX] = xb[g1 + NVOX] + oacc[j][3] * inv1;
    }
}

// ===========================================================================
extern "C" void kernel_launch(void* const* d_in, const int* in_sizes, int n_in,
                              void* d_out, int out_size)
{
    const float* x  = (const float*)d_in[0];
    const float* Wq = (const float*)d_in[1];
    const float* bq = (const float*)d_in[2];
    const float* Wk = (const float*)d_in[3];
    const float* bk = (const float*)d_in[4];
    const float* Wv = (const float*)d_in[5];
    const float* bv = (const float*)d_in[6];
    float* out = (float*)d_out;

    proj_kernel<<<dim3(NVOX / PT_N, 5, BATCH), 256>>>(x, Wq, bq, Wk, bk, Wv, bv);

    cudaFuncSetAttribute(attn_kernel,
                         cudaFuncAttributeMaxDynamicSharedMemorySize, ATTN_SMEM);
    attn_kernel<<<dim3(NVOX / 128, BATCH), 256, ATTN_SMEM>>>(x, out);
}

// round 5
// speedup vs baseline: 4.9450x; 1.1315x over previous
#include <cuda_runtime.h>
#include <cuda_bf16.h>
#include <stdint.h>
#include <math.h>

#define C_DIM 256
#define CQK   32
#define NVOX  4096
#define BATCH 4

// bf16 scratch (static device globals; no allocation anywhere)
__device__ __nv_bfloat16 g_q[BATCH * NVOX * CQK];    // [b][n][cqk]  (pre-scaled by log2e)
__device__ __nv_bfloat16 g_k[BATCH * NVOX * CQK];    // [b][m][cqk]
__device__ __nv_bfloat16 g_v[BATCH * C_DIM * NVOX];  // [b][c][m]  (transposed!)

// ===========================================================================
// Projection kernel: fp32 math, bf16 outputs. V written TRANSPOSED [b][c][m].
// q is scaled by log2(e) so attention can use ex2 directly.
// ===========================================================================
#define PT_N 128
#define PT_M 64
#define PT_K 32
#define WS_PITCH 64
#define LOG2E 1.4426950408889634f

__global__ __launch_bounds__(256) void proj_kernel(
    const float* __restrict__ x,
    const float* __restrict__ Wq, const float* __restrict__ bq,
    const float* __restrict__ Wk, const float* __restrict__ bk,
    const float* __restrict__ Wv, const float* __restrict__ bv)
{
    __shared__ float ws[PT_K * WS_PITCH];
    __shared__ float xs[PT_K * PT_N];

    const int tid = threadIdx.x;
    const int n0  = blockIdx.x * PT_N;
    const int og  = blockIdx.y;
    const int b   = blockIdx.z;
    const int tx  = tid & 7;
    const int ty  = tid >> 3;

    float acc[8][4];
#pragma unroll
    for (int i = 0; i < 8; i++)
#pragma unroll
        for (int j = 0; j < 4; j++) acc[i][j] = 0.f;

    const float* xb = x + (size_t)b * C_DIM * NVOX;

    for (int kk = 0; kk < C_DIM; kk += PT_K) {
        for (int idx = tid; idx < PT_M * PT_K; idx += 256) {
            int k = idx & 31, o = idx >> 5;
            int r = og * PT_M + o;
            const float* wrow;
            if (r < CQK)          wrow = Wq + (size_t)r * C_DIM;
            else if (r < 2 * CQK) wrow = Wk + (size_t)(r - CQK) * C_DIM;
            else                  wrow = Wv + (size_t)(r - 2 * CQK) * C_DIM;
            ws[k * WS_PITCH + o] = wrow[kk + k];
        }
        for (int idx = tid; idx < PT_K * PT_N / 4; idx += 256) {
            int k = idx >> 5, n4 = idx & 31;
            float4 v = *(const float4*)(xb + (size_t)(kk + k) * NVOX + n0 + n4 * 4);
            *(float4*)(xs + k * PT_N + n4 * 4) = v;
        }
        __syncthreads();

#pragma unroll
        for (int k = 0; k < PT_K; k++) {
            const float* wr = ws + k * WS_PITCH + tx * 8;
            float4 w0 = *(const float4*)(wr);
            float4 w1 = *(const float4*)(wr + 4);
            float4 xv = *(const float4*)(xs + k * PT_N + ty * 4);
            float wv[8] = {w0.x, w0.y, w0.z, w0.w, w1.x, w1.y, w1.z, w1.w};
            float xr[4] = {xv.x, xv.y, xv.z, xv.w};
#pragma unroll
            for (int i = 0; i < 8; i++)
#pragma unroll
                for (int j = 0; j < 4; j++)
                    acc[i][j] += wv[i] * xr[j];
        }
        __syncthreads();
    }

#pragma unroll
    for (int i = 0; i < 8; i++) {
        int r = og * PT_M + tx * 8 + i;
#pragma unroll
        for (int j = 0; j < 4; j++) {
            int n = n0 + ty * 4 + j;
            float v = acc[i][j];
            if (r < CQK) {
                g_q[((size_t)b * NVOX + n) * CQK + r] =
                    __float2bfloat16((v + bq[r]) * LOG2E);
            } else if (r < 2 * CQK) {
                g_k[((size_t)b * NVOX + n) * CQK + (r - CQK)] = __float2bfloat16(v + bk[r - CQK]);
            } else {
                int c = r - 2 * CQK;
                g_v[((size_t)b * C_DIM + c) * NVOX + n] = __float2bfloat16(v + bv[c]);
            }
        }
    }
}

// ===========================================================================
// Attention kernel: mma.sync m16n8k16 bf16, max-free base-2 softmax,
// cp.async double-buffered K/V tiles, chunked softmax (low reg pressure),
// smem-staged coalesced epilogue.
// 8 warps x 16 q-rows = BM 128. BK = 128 keys/iter, 32 iters.
// ===========================================================================
#define KP_B  80    // Ks row pitch bytes (conflict-free B-frag loads)
#define VP_B  272   // Vt row pitch bytes (conflict-free B-frag loads)
#define KS_BYTES (128 * KP_B)            // 10240
#define VT_BYTES (256 * VP_B)            // 69632
#define BUF_BYTES (KS_BYTES + VT_BYTES)  // 79872
#define ATTN_SMEM (2 * BUF_BYTES)        // 159744
#define OT_PITCH 132                     // epilogue O-staging pitch (floats)

__device__ __forceinline__ void hmma16816(float* c, const uint32_t* a,
                                          uint32_t b0, uint32_t b1)
{
    asm volatile(
        "mma.sync.aligned.m16n8k16.row.col.f32.bf16.bf16.f32 "
        "{%0,%1,%2,%3}, {%4,%5,%6,%7}, {%8,%9}, {%0,%1,%2,%3};"
        : "+f"(c[0]), "+f"(c[1]), "+f"(c[2]), "+f"(c[3])
        : "r"(a[0]), "r"(a[1]), "r"(a[2]), "r"(a[3]), "r"(b0), "r"(b1));
}

__device__ __forceinline__ float ex2f(float x) {
    float y;
    asm("ex2.approx.ftz.f32 %0, %1;" : "=f"(y) : "f"(x));
    return y;
}

__device__ __forceinline__ void cpa16(uint32_t dst, const void* src) {
    asm volatile("cp.async.cg.shared.global [%0], [%1], 16;"
                 :: "r"(dst), "l"(src));
}
#define CPA_COMMIT() asm volatile("cp.async.commit_group;" ::: "memory")
#define CPA_WAIT(n)  asm volatile("cp.async.wait_group %0;" :: "n"(n) : "memory")

__device__ __forceinline__ uint32_t smem_u32(const void* p) {
    uint32_t a;
    asm("{ .reg .u64 t; cvta.to.shared.u64 t, %1; cvt.u32.u64 %0, t; }"
        : "=r"(a) : "l"(p));
    return a;
}

__global__ __launch_bounds__(256, 1) void attn_kernel(
    const float* __restrict__ x, float* __restrict__ out)
{
    extern __shared__ __align__(16) char smem[];
    const uint32_t sbase = smem_u32(smem);

    const int tid  = threadIdx.x;
    const int w    = tid >> 5;
    const int lane = tid & 31;
    const int g    = lane >> 2;   // row group 0..7
    const int tig  = lane & 3;    // thread-in-group

    const int b    = blockIdx.y;
    const int n0   = blockIdx.x * 128;
    const int wrow = w * 16;

    const __nv_bfloat16* qb = g_q + (size_t)b * NVOX * CQK;
    const __nv_bfloat16* kb = g_k + (size_t)b * NVOX * CQK;
    const __nv_bfloat16* vb = g_v + (size_t)b * C_DIM * NVOX;

    // ---- Q fragments (held all kernel): A-frags for 2 k-tiles of CQK=32
    uint32_t qa[2][4];
    {
        const int r0 = n0 + wrow + g;
#pragma unroll
        for (int kt = 0; kt < 2; kt++) {
            const int cb = kt * 16 + 2 * tig;
            qa[kt][0] = *(const uint32_t*)(qb + (size_t)r0 * CQK + cb);
            qa[kt][1] = *(const uint32_t*)(qb + (size_t)(r0 + 8) * CQK + cb);
            qa[kt][2] = *(const uint32_t*)(qb + (size_t)r0 * CQK + cb + 8);
            qa[kt][3] = *(const uint32_t*)(qb + (size_t)(r0 + 8) * CQK + cb + 8);
        }
    }

    float oacc[32][4];
#pragma unroll
    for (int j = 0; j < 32; j++)
#pragma unroll
        for (int q = 0; q < 4; q++) oacc[j][q] = 0.f;

    float ls0 = 0.f, ls1 = 0.f;   // row sums (rows g and g+8)

    // ---- async tile loader: K (512 x 16B) + V (4096 x 16B) into buffer `buf`
    auto issue_tile = [&](int buf, int m0) {
        const uint32_t kdst = sbase + buf * BUF_BYTES;
        const uint32_t vdst = kdst + KS_BYTES;
#pragma unroll
        for (int i = 0; i < 2; i++) {
            int idx = tid + i * 256;
            int r = idx >> 2, c = idx & 3;
            cpa16(kdst + r * KP_B + c * 16, kb + (size_t)(m0 + r) * CQK + c * 8);
        }
#pragma unroll
        for (int i = 0; i < 16; i++) {
            int idx = tid + i * 256;
            int r = idx >> 4, c = idx & 15;
            cpa16(vdst + r * VP_B + c * 16, vb + (size_t)r * NVOX + m0 + c * 8);
        }
        CPA_COMMIT();
    };

    issue_tile(0, 0);

    for (int it = 0; it < 32; ++it) {
        if (it + 1 < 32) issue_tile((it + 1) & 1, (it + 1) * 128);
        if (it + 1 < 32) { CPA_WAIT(1); } else { CPA_WAIT(0); }
        __syncthreads();

        const char* Ks = smem + (it & 1) * BUF_BYTES;
        const char* Vt = Ks + KS_BYTES;

        // ---- S = Q K^T + exp2, in 4 chunks of 4 n8-tiles (low reg pressure)
        uint32_t pa[8][4];
#pragma unroll
        for (int cc = 0; cc < 4; cc++) {
            float sacc[4][4];
#pragma unroll
            for (int jj = 0; jj < 4; jj++) {
                const int j = cc * 4 + jj;
#pragma unroll
                for (int q = 0; q < 4; q++) sacc[jj][q] = 0.f;
                const char* base = Ks + (8 * j + g) * KP_B + tig * 4;
                uint32_t b0 = *(const uint32_t*)(base);
                uint32_t b1 = *(const uint32_t*)(base + 16);
                uint32_t b2 = *(const uint32_t*)(base + 32);
                uint32_t b3 = *(const uint32_t*)(base + 48);
                hmma16816(sacc[jj], qa[0], b0, b1);
                hmma16816(sacc[jj], qa[1], b2, b3);
            }
            // exp2 (q pre-scaled by log2e) and pack A-frags
#pragma unroll
            for (int kk = 0; kk < 2; kk++) {
                const int kt = cc * 2 + kk;
                float e00 = ex2f(sacc[2 * kk][0]);
                float e01 = ex2f(sacc[2 * kk][1]);
                float e02 = ex2f(sacc[2 * kk][2]);
                float e03 = ex2f(sacc[2 * kk][3]);
                float e10 = ex2f(sacc[2 * kk + 1][0]);
                float e11 = ex2f(sacc[2 * kk + 1][1]);
                float e12 = ex2f(sacc[2 * kk + 1][2]);
                float e13 = ex2f(sacc[2 * kk + 1][3]);
                ls0 += e00 + e01 + e10 + e11;
                ls1 += e02 + e03 + e12 + e13;
                __nv_bfloat162 h;
                h = __float22bfloat162_rn(make_float2(e00, e01));
                pa[kt][0] = *reinterpret_cast<uint32_t*>(&h);
                h = __float22bfloat162_rn(make_float2(e02, e03));
                pa[kt][1] = *reinterpret_cast<uint32_t*>(&h);
                h = __float22bfloat162_rn(make_float2(e10, e11));
                pa[kt][2] = *reinterpret_cast<uint32_t*>(&h);
                h = __float22bfloat162_rn(make_float2(e12, e13));
                pa[kt][3] = *reinterpret_cast<uint32_t*>(&h);
            }
        }

        // ---- O += P V : 32 c n8-tiles x 8 k-tiles
#pragma unroll
        for (int j = 0; j < 32; j++) {
            const char* vbase = Vt + (8 * j + g) * VP_B + tig * 4;
#pragma unroll
            for (int kt = 0; kt < 8; kt++) {
                uint32_t b0 = *(const uint32_t*)(vbase + kt * 32);
                uint32_t b1 = *(const uint32_t*)(vbase + kt * 32 + 16);
                hmma16816(oacc[j], pa[kt], b0, b1);
            }
        }
        __syncthreads();
    }

    // ---- row-sum reduction within lane quad (lanes share row group g)
    ls0 += __shfl_xor_sync(0xFFFFFFFFu, ls0, 1);
    ls0 += __shfl_xor_sync(0xFFFFFFFFu, ls0, 2);
    ls1 += __shfl_xor_sync(0xFFFFFFFFu, ls1, 1);
    ls1 += __shfl_xor_sync(0xFFFFFFFFu, ls1, 2);
    const float inv0 = 1.f / ls0;
    const float inv1 = 1.f / ls1;

    // ---- epilogue: stage O (scaled) into smem, then coalesced gmem stores
    float* Ot = (float*)smem;   // [256 c][OT_PITCH]
#pragma unroll
    for (int j = 0; j < 32; j++) {
        const int c0 = 8 * j + 2 * tig;
        Ot[(c0    ) * OT_PITCH + wrow + g]     = oacc[j][0] * inv0;
        Ot[(c0 + 1) * OT_PITCH + wrow + g]     = oacc[j][1] * inv0;
        Ot[(c0    ) * OT_PITCH + wrow + g + 8] = oacc[j][2] * inv1;
        Ot[(c0 + 1) * OT_PITCH + wrow + g + 8] = oacc[j][3] * inv1;
    }
    __syncthreads();

    const float* xb = x + (size_t)b * C_DIM * NVOX;
    float* ob = out + (size_t)b * C_DIM * NVOX;
    for (int idx = tid; idx < 256 * 128; idx += 256) {
        int n = idx & 127, c = idx >> 7;
        size_t gg = (size_t)c * NVOX + n0 + n;
        ob[gg] = xb[gg] + Ot[c * OT_PITCH + n];
    }
}

// ===========================================================================
extern "C" void kernel_launch(void* const* d_in, const int* in_sizes, int n_in,
                              void* d_out, int out_size)
{
    const float* x  = (const float*)d_in[0];
    const float* Wq = (const float*)d_in[1];
    const float* bq = (const float*)d_in[2];
    const float* Wk = (const float*)d_in[3];
    const float* bk = (const float*)d_in[4];
    const float* Wv = (const float*)d_in[5];
    const float* bv = (const float*)d_in[6];
    float* out = (float*)d_out;

    proj_kernel<<<dim3(NVOX / PT_N, 5, BATCH), 256>>>(x, Wq, bq, Wk, bk, Wv, bv);

    cudaFuncSetAttribute(attn_kernel,
                         cudaFuncAttributeMaxDynamicSharedMemorySize, ATTN_SMEM);
    attn_kernel<<<dim3(NVOX / 128, BATCH), 256, ATTN_SMEM>>>(x, out);
}

// round 6
// speedup vs baseline: 5.4349x; 1.0991x over previous
#include <cuda_runtime.h>
#include <cuda_bf16.h>
#include <stdint.h>
#include <math.h>

#define C_DIM 256
#define CQK   32
#define NVOX  4096
#define BATCH 4

// bf16 scratch (static device globals; no allocation anywhere)
__device__ __nv_bfloat16 g_q[BATCH * NVOX * CQK];    // [b][n][cqk] (pre-scaled by log2e)
__device__ __nv_bfloat16 g_k[BATCH * NVOX * CQK];    // [b][m][cqk]
__device__ __nv_bfloat16 g_v[BATCH * NVOX * C_DIM];  // [b][m][c]  (row-major)

#define LOG2E 1.4426950408889634f

// ===========================================================================
// Projection kernel: fp32 math, bf16 outputs, 16B packed stores.
// ===========================================================================
#define PT_N 128
#define PT_M 64
#define PT_K 32
#define WS_PITCH 64

__global__ __launch_bounds__(256) void proj_kernel(
    const float* __restrict__ x,
    const float* __restrict__ Wq, const float* __restrict__ bq,
    const float* __restrict__ Wk, const float* __restrict__ bk,
    const float* __restrict__ Wv, const float* __restrict__ bv)
{
    __shared__ float ws[PT_K * WS_PITCH];
    __shared__ float xs[PT_K * PT_N];

    const int tid = threadIdx.x;
    const int n0  = blockIdx.x * PT_N;
    const int og  = blockIdx.y;
    const int b   = blockIdx.z;
    const int tx  = tid & 7;
    const int ty  = tid >> 3;

    float acc[8][4];
#pragma unroll
    for (int i = 0; i < 8; i++)
#pragma unroll
        for (int j = 0; j < 4; j++) acc[i][j] = 0.f;

    const float* xb = x + (size_t)b * C_DIM * NVOX;

    for (int kk = 0; kk < C_DIM; kk += PT_K) {
        for (int idx = tid; idx < PT_M * PT_K; idx += 256) {
            int k = idx & 31, o = idx >> 5;
            int r = og * PT_M + o;
            const float* wrow;
            if (r < CQK)          wrow = Wq + (size_t)r * C_DIM;
            else if (r < 2 * CQK) wrow = Wk + (size_t)(r - CQK) * C_DIM;
            else                  wrow = Wv + (size_t)(r - 2 * CQK) * C_DIM;
            ws[k * WS_PITCH + o] = wrow[kk + k];
        }
        for (int idx = tid; idx < PT_K * PT_N / 4; idx += 256) {
            int k = idx >> 5, n4 = idx & 31;
            float4 v = *(const float4*)(xb + (size_t)(kk + k) * NVOX + n0 + n4 * 4);
            *(float4*)(xs + k * PT_N + n4 * 4) = v;
        }
        __syncthreads();

#pragma unroll
        for (int k = 0; k < PT_K; k++) {
            const float* wr = ws + k * WS_PITCH + tx * 8;
            float4 w0 = *(const float4*)(wr);
            float4 w1 = *(const float4*)(wr + 4);
            float4 xv = *(const float4*)(xs + k * PT_N + ty * 4);
            float wv[8] = {w0.x, w0.y, w0.z, w0.w, w1.x, w1.y, w1.z, w1.w};
            float xr[4] = {xv.x, xv.y, xv.z, xv.w};
#pragma unroll
            for (int i = 0; i < 8; i++)
#pragma unroll
                for (int j = 0; j < 4; j++)
                    acc[i][j] += wv[i] * xr[j];
        }
        __syncthreads();
    }

    // epilogue: pack 8 outputs (contiguous last-dim) into one 16B store per n
    if (og == 0) {
        // rows 0..63: q (tx<4) or k
        const bool isq = (tx < 4);
        const int rb = isq ? tx * 8 : tx * 8 - 32;
        const float* bias = isq ? bq : bk;
        __nv_bfloat16* dst = isq ? g_q : g_k;
        float bs[8];
#pragma unroll
        for (int i = 0; i < 8; i++) bs[i] = bias[rb + i];
#pragma unroll
        for (int j = 0; j < 4; j++) {
            int n = n0 + ty * 4 + j;
            __nv_bfloat162 h[4];
#pragma unroll
            for (int t = 0; t < 4; t++) {
                float v0 = acc[2 * t][j] + bs[2 * t];
                float v1 = acc[2 * t + 1][j] + bs[2 * t + 1];
                if (isq) { v0 *= LOG2E; v1 *= LOG2E; }
                h[t] = __float22bfloat162_rn(make_float2(v0, v1));
            }
            *(uint4*)(dst + ((size_t)b * NVOX + n) * CQK + rb) = *(uint4*)h;
        }
    } else {
        const int c0 = og * PT_M + tx * 8 - 64;
        float bs[8];
#pragma unroll
        for (int i = 0; i < 8; i++) bs[i] = bv[c0 + i];
#pragma unroll
        for (int j = 0; j < 4; j++) {
            int m = n0 + ty * 4 + j;
            __nv_bfloat162 h[4];
#pragma unroll
            for (int t = 0; t < 4; t++)
                h[t] = __float22bfloat162_rn(make_float2(
                    acc[2 * t][j] + bs[2 * t], acc[2 * t + 1][j] + bs[2 * t + 1]));
            *(uint4*)(g_v + ((size_t)b * NVOX + m) * C_DIM + c0) = *(uint4*)h;
        }
    }
}

// ===========================================================================
// Attention kernel: mma.sync m16n8k16 bf16, ldmatrix B-frags, max-free
// base-2 softmax, cp.async double-buffered K/V tiles.
// 8 warps x 16 q-rows = BM 128. BK = 128 keys/iter, 32 iters.
// ===========================================================================
#define KP_B  80    // Ks row pitch bytes (5x16B -> conflict-free LDSM)
#define VP_B  528   // Vt row pitch bytes (33x16B -> conflict-free LDSM.trans)
#define KS_BYTES (128 * KP_B)            // 10240
#define VT_BYTES (128 * VP_B)            // 67584
#define BUF_BYTES (KS_BYTES + VT_BYTES)  // 77824
#define ATTN_SMEM (2 * BUF_BYTES)        // 155648
#define OT_PITCH 132                     // epilogue O-staging pitch (floats)

__device__ __forceinline__ void hmma16816(float* c, const uint32_t* a,
                                          uint32_t b0, uint32_t b1)
{
    asm volatile(
        "mma.sync.aligned.m16n8k16.row.col.f32.bf16.bf16.f32 "
        "{%0,%1,%2,%3}, {%4,%5,%6,%7}, {%8,%9}, {%0,%1,%2,%3};"
        : "+f"(c[0]), "+f"(c[1]), "+f"(c[2]), "+f"(c[3])
        : "r"(a[0]), "r"(a[1]), "r"(a[2]), "r"(a[3]), "r"(b0), "r"(b1));
}

__device__ __forceinline__ void ldsm4(uint32_t* r, uint32_t addr) {
    asm volatile("ldmatrix.sync.aligned.m8n8.x4.shared.b16 {%0,%1,%2,%3}, [%4];"
                 : "=r"(r[0]), "=r"(r[1]), "=r"(r[2]), "=r"(r[3]) : "r"(addr));
}
__device__ __forceinline__ void ldsm4t(uint32_t* r, uint32_t addr) {
    asm volatile("ldmatrix.sync.aligned.m8n8.x4.trans.shared.b16 {%0,%1,%2,%3}, [%4];"
                 : "=r"(r[0]), "=r"(r[1]), "=r"(r[2]), "=r"(r[3]) : "r"(addr));
}

__device__ __forceinline__ float ex2f(float x) {
    float y;
    asm("ex2.approx.ftz.f32 %0, %1;" : "=f"(y) : "f"(x));
    return y;
}

__device__ __forceinline__ void cpa16(uint32_t dst, const void* src) {
    asm volatile("cp.async.cg.shared.global [%0], [%1], 16;"
                 :: "r"(dst), "l"(src));
}
#define CPA_COMMIT() asm volatile("cp.async.commit_group;" ::: "memory")
#define CPA_WAIT(n)  asm volatile("cp.async.wait_group %0;" :: "n"(n) : "memory")

__device__ __forceinline__ uint32_t smem_u32(const void* p) {
    uint32_t a;
    asm("{ .reg .u64 t; cvta.to.shared.u64 t, %1; cvt.u32.u64 %0, t; }"
        : "=r"(a) : "l"(p));
    return a;
}

__global__ __launch_bounds__(256, 1) void attn_kernel(
    const float* __restrict__ x, float* __restrict__ out)
{
    extern __shared__ __align__(16) char smem[];
    const uint32_t sbase = smem_u32(smem);

    const int tid  = threadIdx.x;
    const int w    = tid >> 5;
    const int lane = tid & 31;
    const int g    = lane >> 2;   // row group 0..7
    const int tig  = lane & 3;    // thread-in-group

    const int b    = blockIdx.y;
    const int n0   = blockIdx.x * 128;
    const int wrow = w * 16;

    const __nv_bfloat16* qb = g_q + (size_t)b * NVOX * CQK;
    const __nv_bfloat16* kb = g_k + (size_t)b * NVOX * CQK;
    const __nv_bfloat16* vb = g_v + (size_t)b * NVOX * C_DIM;

    // ---- Q fragments (held all kernel): A-frags for 2 k-tiles of CQK=32
    uint32_t qa[2][4];
    {
        const int r0 = n0 + wrow + g;
#pragma unroll
        for (int kt = 0; kt < 2; kt++) {
            const int cb = kt * 16 + 2 * tig;
            qa[kt][0] = *(const uint32_t*)(qb + (size_t)r0 * CQK + cb);
            qa[kt][1] = *(const uint32_t*)(qb + (size_t)(r0 + 8) * CQK + cb);
            qa[kt][2] = *(const uint32_t*)(qb + (size_t)r0 * CQK + cb + 8);
            qa[kt][3] = *(const uint32_t*)(qb + (size_t)(r0 + 8) * CQK + cb + 8);
        }
    }

    float oacc[32][4];
#pragma unroll
    for (int j = 0; j < 32; j++)
#pragma unroll
        for (int q = 0; q < 4; q++) oacc[j][q] = 0.f;

    float ls0 = 0.f, ls1 = 0.f;

    // ---- async tile loader: K (512 x 16B) + V (4096 x 16B)
    auto issue_tile = [&](int buf, int m0) {
        const uint32_t kdst = sbase + buf * BUF_BYTES;
        const uint32_t vdst = kdst + KS_BYTES;
#pragma unroll
        for (int i = 0; i < 2; i++) {
            int idx = tid + i * 256;
            int r = idx >> 2, c = idx & 3;
            cpa16(kdst + r * KP_B + c * 16, kb + (size_t)(m0 + r) * CQK + c * 8);
        }
#pragma unroll
        for (int i = 0; i < 16; i++) {
            int idx = tid + i * 256;
            int r = idx >> 5, c = idx & 31;   // row = m, 512B contiguous
            cpa16(vdst + r * VP_B + c * 16, vb + (size_t)(m0 + r) * C_DIM + c * 8);
        }
        CPA_COMMIT();
    };

    issue_tile(0, 0);

    // per-lane ldmatrix addresses (row part), hoisted
    const int l8 = lane & 7, l8g = lane >> 3;

    for (int it = 0; it < 32; ++it) {
        if (it + 1 < 32) issue_tile((it + 1) & 1, (it + 1) * 128);
        if (it + 1 < 32) { CPA_WAIT(1); } else { CPA_WAIT(0); }
        __syncthreads();

        const uint32_t ksb = sbase + (it & 1) * BUF_BYTES;
        const uint32_t vtb = ksb + KS_BYTES;

        // ---- S = Q K^T + exp2, 4 chunks of 4 n8-tiles
        uint32_t pa[8][4];
#pragma unroll
        for (int cc = 0; cc < 4; cc++) {
            float sacc[4][4];
#pragma unroll
            for (int jj = 0; jj < 4; jj++) {
                const int j = cc * 4 + jj;
#pragma unroll
                for (int q = 0; q < 4; q++) sacc[jj][q] = 0.f;
                uint32_t kf[4];
                ldsm4(kf, ksb + (uint32_t)((8 * j + l8) * KP_B + l8g * 16));
                hmma16816(sacc[jj], qa[0], kf[0], kf[1]);
                hmma16816(sacc[jj], qa[1], kf[2], kf[3]);
            }
#pragma unroll
            for (int kk = 0; kk < 2; kk++) {
                const int kt = cc * 2 + kk;
                float e00 = ex2f(sacc[2 * kk][0]);
                float e01 = ex2f(sacc[2 * kk][1]);
                float e02 = ex2f(sacc[2 * kk][2]);
                float e03 = ex2f(sacc[2 * kk][3]);
                float e10 = ex2f(sacc[2 * kk + 1][0]);
                float e11 = ex2f(sacc[2 * kk + 1][1]);
                float e12 = ex2f(sacc[2 * kk + 1][2]);
                float e13 = ex2f(sacc[2 * kk + 1][3]);
                ls0 += e00 + e01 + e10 + e11;
                ls1 += e02 + e03 + e12 + e13;
                __nv_bfloat162 h;
                h = __float22bfloat162_rn(make_float2(e00, e01));
                pa[kt][0] = *reinterpret_cast<uint32_t*>(&h);
                h = __float22bfloat162_rn(make_float2(e02, e03));
                pa[kt][1] = *reinterpret_cast<uint32_t*>(&h);
                h = __float22bfloat162_rn(make_float2(e10, e11));
                pa[kt][2] = *reinterpret_cast<uint32_t*>(&h);
                h = __float22bfloat162_rn(make_float2(e12, e13));
                pa[kt][3] = *reinterpret_cast<uint32_t*>(&h);
            }
        }

        // ---- O += P V : 32 c n8-tiles; V B-frags via ldmatrix.trans
#pragma unroll
        for (int j = 0; j < 32; j++) {
#pragma unroll
            for (int q = 0; q < 4; q++) {
                uint32_t vf[4];
                ldsm4t(vf, vtb + (uint32_t)((q * 32 + lane) * VP_B + j * 16));
                hmma16816(oacc[j], pa[2 * q],     vf[0], vf[1]);
                hmma16816(oacc[j], pa[2 * q + 1], vf[2], vf[3]);
            }
        }
        __syncthreads();
    }

    // ---- row-sum reduction within lane quad
    ls0 += __shfl_xor_sync(0xFFFFFFFFu, ls0, 1);
    ls0 += __shfl_xor_sync(0xFFFFFFFFu, ls0, 2);
    ls1 += __shfl_xor_sync(0xFFFFFFFFu, ls1, 1);
    ls1 += __shfl_xor_sync(0xFFFFFFFFu, ls1, 2);
    const float inv0 = 1.f / ls0;
    const float inv1 = 1.f / ls1;

    // ---- epilogue: stage O (scaled) into smem, then coalesced gmem stores
    float* Ot = (float*)smem;   // [256 c][OT_PITCH]
    __syncthreads();
#pragma unroll
    for (int j = 0; j < 32; j++) {
        const int c0 = 8 * j + 2 * tig;
        Ot[(c0    ) * OT_PITCH + wrow + g]     = oacc[j][0] * inv0;
        Ot[(c0 + 1) * OT_PITCH + wrow + g]     = oacc[j][1] * inv0;
        Ot[(c0    ) * OT_PITCH + wrow + g + 8] = oacc[j][2] * inv1;
        Ot[(c0 + 1) * OT_PITCH + wrow + g + 8] = oacc[j][3] * inv1;
    }
    __syncthreads();

    const float* xb = x + (size_t)b * C_DIM * NVOX;
    float* ob = out + (size_t)b * C_DIM * NVOX;
    for (int idx = tid; idx < 256 * 128; idx += 256) {
        int n = idx & 127, c = idx >> 7;
        size_t gg = (size_t)c * NVOX + n0 + n;
        ob[gg] = xb[gg] + Ot[c * OT_PITCH + n];
    }
}

// ===========================================================================
extern "C" void kernel_launch(void* const* d_in, const int* in_sizes, int n_in,
                              void* d_out, int out_size)
{
    const float* x  = (const float*)d_in[0];
    const float* Wq = (const float*)d_in[1];
    const float* bq = (const float*)d_in[2];
    const float* Wk = (const float*)d_in[3];
    const float* bk = (const float*)d_in[4];
    const float* Wv = (const float*)d_in[5];
    const float* bv = (const float*)d_in[6];
    float* out = (float*)d_out;

    proj_kernel<<<dim3(NVOX / PT_N, 5, BATCH), 256>>>(x, Wq, bq, Wk, bk, Wv, bv);

    cudaFuncSetAttribute(attn_kernel,
                         cudaFuncAttributeMaxDynamicSharedMemorySize, ATTN_SMEM);
    attn_kernel<<<dim3(NVOX / 128, BATCH), 256, ATTN_SMEM>>>(x, out);
}

// round 7
// speedup vs baseline: 10.2870x; 1.8928x over previous
#include <cuda_runtime.h>
#include <cuda_bf16.h>
#include <stdint.h>
#include <math.h>

#define C_DIM 256
#define CQK   32
#define NVOX  4096
#define BATCH 4

// bf16 scratch (static device globals; no allocation anywhere)
__device__ __nv_bfloat16 g_q[BATCH * NVOX * CQK];    // [b][n][cqk] (pre-scaled by log2e)
__device__ __nv_bfloat16 g_k[BATCH * NVOX * CQK];    // [b][m][cqk]
__device__ __nv_bfloat16 g_v[BATCH * NVOX * C_DIM];  // [b][m][c]  (row-major)

#define LOG2E 1.4426950408889634f

// ---------------------------------------------------------------------------
// Common PTX helpers
// ---------------------------------------------------------------------------
__device__ __forceinline__ void hmma16816(float* c, const uint32_t* a,
                                          uint32_t b0, uint32_t b1)
{
    asm volatile(
        "mma.sync.aligned.m16n8k16.row.col.f32.bf16.bf16.f32 "
        "{%0,%1,%2,%3}, {%4,%5,%6,%7}, {%8,%9}, {%0,%1,%2,%3};"
        : "+f"(c[0]), "+f"(c[1]), "+f"(c[2]), "+f"(c[3])
        : "r"(a[0]), "r"(a[1]), "r"(a[2]), "r"(a[3]), "r"(b0), "r"(b1));
}
__device__ __forceinline__ void ldsm4(uint32_t* r, uint32_t addr) {
    asm volatile("ldmatrix.sync.aligned.m8n8.x4.shared.b16 {%0,%1,%2,%3}, [%4];"
                 : "=r"(r[0]), "=r"(r[1]), "=r"(r[2]), "=r"(r[3]) : "r"(addr));
}
__device__ __forceinline__ void ldsm4t(uint32_t* r, uint32_t addr) {
    asm volatile("ldmatrix.sync.aligned.m8n8.x4.trans.shared.b16 {%0,%1,%2,%3}, [%4];"
                 : "=r"(r[0]), "=r"(r[1]), "=r"(r[2]), "=r"(r[3]) : "r"(addr));
}
__device__ __forceinline__ float ex2f(float x) {
    float y;
    asm("ex2.approx.ftz.f32 %0, %1;" : "=f"(y) : "f"(x));
    return y;
}
__device__ __forceinline__ void cpa16(uint32_t dst, const void* src) {
    asm volatile("cp.async.cg.shared.global [%0], [%1], 16;"
                 :: "r"(dst), "l"(src));
}
#define CPA_COMMIT() asm volatile("cp.async.commit_group;" ::: "memory")
#define CPA_WAIT(n)  asm volatile("cp.async.wait_group %0;" :: "n"(n) : "memory")
__device__ __forceinline__ uint32_t smem_u32(const void* p) {
    uint32_t a;
    asm("{ .reg .u64 t; cvta.to.shared.u64 t, %1; cvt.u32.u64 %0, t; }"
        : "=r"(a) : "l"(p));
    return a;
}

// ===========================================================================
// Projection kernel v2: bf16 tensor-core GEMM.
// Per CTA: [64 out-rows x 256 voxels], K=256 in 4 chunks of 64.
// W and x converted fp32->bf16 into smem; epilogue staged for coalesced stores.
// ===========================================================================
#define WP_EL 264   // Wt pitch elems (528 B = 33 x 16B -> conflict-free ldsm)
#define XP_EL 264   // xs pitch elems
#define ST_EL 96    // staging pitch elems (192 B = 64 mod 128 -> conflict-free)
#define PJ_SMEM (64 * WP_EL * 2 + 64 * XP_EL * 2 + 256)   // 67840 B

__global__ __launch_bounds__(256) void proj_kernel(
    const float* __restrict__ x,
    const float* __restrict__ Wq, const float* __restrict__ bq,
    const float* __restrict__ Wk, const float* __restrict__ bk,
    const float* __restrict__ Wv, const float* __restrict__ bv)
{
    extern __shared__ __align__(16) char psm[];
    __nv_bfloat16* Wt = (__nv_bfloat16*)psm;                       // [64 o][WP_EL]
    __nv_bfloat16* xs = (__nv_bfloat16*)(psm + 64 * WP_EL * 2);    // [64 k][XP_EL]
    float* bs = (float*)(psm + 64 * WP_EL * 2 + 64 * XP_EL * 2);   // [64]
    const uint32_t wbase = smem_u32(Wt);
    const uint32_t xbase = smem_u32(xs);

    const int tid  = threadIdx.x;
    const int lane = tid & 31;
    const int w    = tid >> 5;
    const int g    = lane >> 2;
    const int tig  = lane & 3;
    const int wm   = w & 1;      // m half (32 out-rows)
    const int wn   = w >> 1;     // n quarter (64 voxels)

    const int n0 = blockIdx.x * 256;
    const int og = blockIdx.y;
    const int b  = blockIdx.z;

    const float* xb = x + (size_t)b * C_DIM * NVOX;

    // ---- convert W slice (64 rows x 256 k) to bf16 smem
#pragma unroll
    for (int i = 0; i < 16; i++) {
        int idx = tid + i * 256;
        int o = idx >> 6, k4 = idx & 63;
        int r = og * 64 + o;
        const float* wrow;
        if (r < CQK)          wrow = Wq + (size_t)r * C_DIM;
        else if (r < 2 * CQK) wrow = Wk + (size_t)(r - CQK) * C_DIM;
        else                  wrow = Wv + (size_t)(r - 2 * CQK) * C_DIM;
        float4 v = *(const float4*)(wrow + k4 * 4);
        __nv_bfloat162 h0 = __float22bfloat162_rn(make_float2(v.x, v.y));
        __nv_bfloat162 h1 = __float22bfloat162_rn(make_float2(v.z, v.w));
        *(__nv_bfloat162*)(Wt + o * WP_EL + k4 * 4)     = h0;
        *(__nv_bfloat162*)(Wt + o * WP_EL + k4 * 4 + 2) = h1;
    }
    // ---- bias table
    if (tid < 64) {
        int r = og * 64 + tid;
        float bb;
        if (r < CQK)          bb = bq[r];
        else if (r < 2 * CQK) bb = bk[r - CQK];
        else                  bb = bv[r - 2 * CQK];
        bs[tid] = bb;
    }

    float cacc[2][8][4];
#pragma unroll
    for (int mt = 0; mt < 2; mt++)
#pragma unroll
        for (int nt = 0; nt < 8; nt++)
#pragma unroll
            for (int q = 0; q < 4; q++) cacc[mt][nt][q] = 0.f;

    for (int kc = 0; kc < 4; kc++) {
        __syncthreads();
        // load x chunk [64 k][256 n] fp32 -> bf16 smem
#pragma unroll
        for (int i = 0; i < 16; i++) {
            int idx = tid + i * 256;
            int kr = idx >> 6, c4 = idx & 63;
            float4 v = *(const float4*)(xb + (size_t)(kc * 64 + kr) * NVOX + n0 + c4 * 4);
            __nv_bfloat162 h0 = __float22bfloat162_rn(make_float2(v.x, v.y));
            __nv_bfloat162 h1 = __float22bfloat162_rn(make_float2(v.z, v.w));
            *(__nv_bfloat162*)(xs + kr * XP_EL + c4 * 4)     = h0;
            *(__nv_bfloat162*)(xs + kr * XP_EL + c4 * 4 + 2) = h1;
        }
        __syncthreads();

#pragma unroll
        for (int kh = 0; kh < 2; kh++) {
            // A-frags: [mt][k16 pair within this k32]
            uint32_t af[2][2][4];
#pragma unroll
            for (int mt = 0; mt < 2; mt++)
#pragma unroll
                for (int kk = 0; kk < 2; kk++) {
                    int col16 = kc * 8 + kh * 4 + kk * 2 + (lane >> 4);
                    int row = wm * 32 + mt * 16 + (lane & 15);
                    ldsm4(af[mt][kk], wbase + (uint32_t)(row * (WP_EL * 2) + col16 * 16));
                }
#pragma unroll
            for (int nt = 0; nt < 8; nt++) {
                uint32_t xf[4];
                ldsm4t(xf, xbase + (uint32_t)((kh * 32 + lane) * (XP_EL * 2)
                                              + (wn * 8 + nt) * 16));
#pragma unroll
                for (int mt = 0; mt < 2; mt++) {
                    hmma16816(cacc[mt][nt], af[mt][0], xf[0], xf[1]);
                    hmma16816(cacc[mt][nt], af[mt][1], xf[2], xf[3]);
                }
            }
        }
    }
    __syncthreads();

    // ---- stage C transposed: stage[n(256)][r(64)] bf16, pitch ST_EL
    __nv_bfloat16* st = (__nv_bfloat16*)psm;
    const float sc = (og == 0 && wm == 0) ? LOG2E : 1.f;
    const int r0 = wm * 32 + g;
#pragma unroll
    for (int mt = 0; mt < 2; mt++) {
        const int ra = r0 + mt * 16, rb = ra + 8;
        const float ba = bs[ra], bb2 = bs[rb];
#pragma unroll
        for (int nt = 0; nt < 8; nt++) {
            const int c0 = wn * 64 + nt * 8 + 2 * tig;
            st[(c0    ) * ST_EL + ra] = __float2bfloat16((cacc[mt][nt][0] + ba) * sc);
            st[(c0 + 1) * ST_EL + ra] = __float2bfloat16((cacc[mt][nt][1] + ba) * sc);
            st[(c0    ) * ST_EL + rb] = __float2bfloat16((cacc[mt][nt][2] + bb2) * sc);
            st[(c0 + 1) * ST_EL + rb] = __float2bfloat16((cacc[mt][nt][3] + bb2) * sc);
        }
    }
    __syncthreads();

    // ---- coalesced gmem stores
    if (og == 0) {
        // rows 0..31 -> q, rows 32..63 -> k   (both [n][32] layouts)
#pragma unroll
        for (int p = 0; p < 4; p++) {
            int nl = p * 64 + (tid >> 2);
            int ch = tid & 3;
            uint4 qv = *(const uint4*)(st + nl * ST_EL + ch * 8);
            uint4 kv = *(const uint4*)(st + nl * ST_EL + 32 + ch * 8);
            size_t base = ((size_t)b * NVOX + n0 + nl) * CQK + ch * 8;
            *(uint4*)(g_q + base) = qv;
            *(uint4*)(g_k + base) = kv;
        }
    } else {
        const int cb = og * 64 - 64;
#pragma unroll
        for (int p = 0; p < 8; p++) {
            int nl = p * 32 + (tid >> 3);
            int ch = tid & 7;
            uint4 vv = *(const uint4*)(st + nl * ST_EL + ch * 8);
            *(uint4*)(g_v + ((size_t)b * NVOX + n0 + nl) * C_DIM + cb + ch * 8) = vv;
        }
    }
}

// ===========================================================================
// Attention kernel: mma.sync m16n8k16 bf16, ldmatrix B-frags, max-free
// base-2 softmax, cp.async double-buffered K/V tiles. (unchanged from R6)
// ===========================================================================
#define KP_B  80
#define VP_B  528
#define KS_BYTES (128 * KP_B)
#define VT_BYTES (128 * VP_B)
#define BUF_BYTES (KS_BYTES + VT_BYTES)
#define ATTN_SMEM (2 * BUF_BYTES)
#define OT_PITCH 132

__global__ __launch_bounds__(256, 1) void attn_kernel(
    const float* __restrict__ x, float* __restrict__ out)
{
    extern __shared__ __align__(16) char smem[];
    const uint32_t sbase = smem_u32(smem);

    const int tid  = threadIdx.x;
    const int w    = tid >> 5;
    const int lane = tid & 31;
    const int g    = lane >> 2;
    const int tig  = lane & 3;

    const int b    = blockIdx.y;
    const int n0   = blockIdx.x * 128;
    const int wrow = w * 16;

    const __nv_bfloat16* qb = g_q + (size_t)b * NVOX * CQK;
    const __nv_bfloat16* kb = g_k + (size_t)b * NVOX * CQK;
    const __nv_bfloat16* vb = g_v + (size_t)b * NVOX * C_DIM;

    uint32_t qa[2][4];
    {
        const int r0 = n0 + wrow + g;
#pragma unroll
        for (int kt = 0; kt < 2; kt++) {
            const int cb = kt * 16 + 2 * tig;
            qa[kt][0] = *(const uint32_t*)(qb + (size_t)r0 * CQK + cb);
            qa[kt][1] = *(const uint32_t*)(qb + (size_t)(r0 + 8) * CQK + cb);
            qa[kt][2] = *(const uint32_t*)(qb + (size_t)r0 * CQK + cb + 8);
            qa[kt][3] = *(const uint32_t*)(qb + (size_t)(r0 + 8) * CQK + cb + 8);
        }
    }

    float oacc[32][4];
#pragma unroll
    for (int j = 0; j < 32; j++)
#pragma unroll
        for (int q = 0; q < 4; q++) oacc[j][q] = 0.f;

    float ls0 = 0.f, ls1 = 0.f;

    auto issue_tile = [&](int buf, int m0) {
        const uint32_t kdst = sbase + buf * BUF_BYTES;
        const uint32_t vdst = kdst + KS_BYTES;
#pragma unroll
        for (int i = 0; i < 2; i++) {
            int idx = tid + i * 256;
            int r = idx >> 2, c = idx & 3;
            cpa16(kdst + r * KP_B + c * 16, kb + (size_t)(m0 + r) * CQK + c * 8);
        }
#pragma unroll
        for (int i = 0; i < 16; i++) {
            int idx = tid + i * 256;
            int r = idx >> 5, c = idx & 31;
            cpa16(vdst + r * VP_B + c * 16, vb + (size_t)(m0 + r) * C_DIM + c * 8);
        }
        CPA_COMMIT();
    };

    issue_tile(0, 0);

    const int l8 = lane & 7, l8g = lane >> 3;

    for (int it = 0; it < 32; ++it) {
        if (it + 1 < 32) issue_tile((it + 1) & 1, (it + 1) * 128);
        if (it + 1 < 32) { CPA_WAIT(1); } else { CPA_WAIT(0); }
        __syncthreads();

        const uint32_t ksb = sbase + (it & 1) * BUF_BYTES;
        const uint32_t vtb = ksb + KS_BYTES;

        uint32_t pa[8][4];
#pragma unroll
        for (int cc = 0; cc < 4; cc++) {
            float sacc[4][4];
#pragma unroll
            for (int jj = 0; jj < 4; jj++) {
                const int j = cc * 4 + jj;
#pragma unroll
                for (int q = 0; q < 4; q++) sacc[jj][q] = 0.f;
                uint32_t kf[4];
                ldsm4(kf, ksb + (uint32_t)((8 * j + l8) * KP_B + l8g * 16));
                hmma16816(sacc[jj], qa[0], kf[0], kf[1]);
                hmma16816(sacc[jj], qa[1], kf[2], kf[3]);
            }
#pragma unroll
            for (int kk = 0; kk < 2; kk++) {
                const int kt = cc * 2 + kk;
                float e00 = ex2f(sacc[2 * kk][0]);
                float e01 = ex2f(sacc[2 * kk][1]);
                float e02 = ex2f(sacc[2 * kk][2]);
                float e03 = ex2f(sacc[2 * kk][3]);
                float e10 = ex2f(sacc[2 * kk + 1][0]);
                float e11 = ex2f(sacc[2 * kk + 1][1]);
                float e12 = ex2f(sacc[2 * kk + 1][2]);
                float e13 = ex2f(sacc[2 * kk + 1][3]);
                ls0 += e00 + e01 + e10 + e11;
                ls1 += e02 + e03 + e12 + e13;
                __nv_bfloat162 h;
                h = __float22bfloat162_rn(make_float2(e00, e01));
                pa[kt][0] = *reinterpret_cast<uint32_t*>(&h);
                h = __float22bfloat162_rn(make_float2(e02, e03));
                pa[kt][1] = *reinterpret_cast<uint32_t*>(&h);
                h = __float22bfloat162_rn(make_float2(e10, e11));
                pa[kt][2] = *reinterpret_cast<uint32_t*>(&h);
                h = __float22bfloat162_rn(make_float2(e12, e13));
                pa[kt][3] = *reinterpret_cast<uint32_t*>(&h);
            }
        }

#pragma unroll
        for (int j = 0; j < 32; j++) {
#pragma unroll
            for (int q = 0; q < 4; q++) {
                uint32_t vf[4];
                ldsm4t(vf, vtb + (uint32_t)((q * 32 + lane) * VP_B + j * 16));
                hmma16816(oacc[j], pa[2 * q],     vf[0], vf[1]);
                hmma16816(oacc[j], pa[2 * q + 1], vf[2], vf[3]);
            }
        }
        __syncthreads();
    }

    ls0 += __shfl_xor_sync(0xFFFFFFFFu, ls0, 1);
    ls0 += __shfl_xor_sync(0xFFFFFFFFu, ls0, 2);
    ls1 += __shfl_xor_sync(0xFFFFFFFFu, ls1, 1);
    ls1 += __shfl_xor_sync(0xFFFFFFFFu, ls1, 2);
    const float inv0 = 1.f / ls0;
    const float inv1 = 1.f / ls1;

    float* Ot = (float*)smem;
    __syncthreads();
#pragma unroll
    for (int j = 0; j < 32; j++) {
        const int c0 = 8 * j + 2 * tig;
        Ot[(c0    ) * OT_PITCH + wrow + g]     = oacc[j][0] * inv0;
        Ot[(c0 + 1) * OT_PITCH + wrow + g]     = oacc[j][1] * inv0;
        Ot[(c0    ) * OT_PITCH + wrow + g + 8] = oacc[j][2] * inv1;
        Ot[(c0 + 1) * OT_PITCH + wrow + g + 8] = oacc[j][3] * inv1;
    }
    __syncthreads();

    const float* xb = x + (size_t)b * C_DIM * NVOX;
    float* ob = out + (size_t)b * C_DIM * NVOX;
    for (int idx = tid; idx < 256 * 128; idx += 256) {
        int n = idx & 127, c = idx >> 7;
        size_t gg = (size_t)c * NVOX + n0 + n;
        ob[gg] = xb[gg] + Ot[c * OT_PITCH + n];
    }
}

// ===========================================================================
extern "C" void kernel_launch(void* const* d_in, const int* in_sizes, int n_in,
                              void* d_out, int out_size)
{
    const float* x  = (const float*)d_in[0];
    const float* Wq = (const float*)d_in[1];
    const float* bq = (const float*)d_in[2];
    const float* Wk = (const float*)d_in[3];
    const float* bk = (const float*)d_in[4];
    const float* Wv = (const float*)d_in[5];
    const float* bv = (const float*)d_in[6];
    float* out = (float*)d_out;

    cudaFuncSetAttribute(proj_kernel,
                         cudaFuncAttributeMaxDynamicSharedMemorySize, PJ_SMEM);
    proj_kernel<<<dim3(NVOX / 256, 5, BATCH), 256, PJ_SMEM>>>(
        x, Wq, bq, Wk, bk, Wv, bv);

    cudaFuncSetAttribute(attn_kernel,
                         cudaFuncAttributeMaxDynamicSharedMemorySize, ATTN_SMEM);
    attn_kernel<<<dim3(NVOX / 128, BATCH), 256, ATTN_SMEM>>>(x, out);
}